// round 12
// baseline (speedup 1.0000x reference)
#include <cuda_runtime.h>
#include <cuda_bf16.h>
#include <cstdint>

#define NSEQ 2048
#define DH   64
#define NBH  32      // B*H
#define EPSM 1.928749848e-22f   // expf(-50)

static __device__ float g_l[NBH * NSEQ];

// pack2(lo, hi): low 16 bits = bf16(lo), high = bf16(hi)
__device__ __forceinline__ uint32_t pack2(float lo, float hi) {
    uint32_t r;  // PTX: first src -> high half, second -> low half
    asm("cvt.rn.bf16x2.f32 %0, %1, %2;" : "=r"(r) : "f"(hi), "f"(lo));
    return r;
}

// portable warp-level bf16 MMA, fp32 accum (sm_80+; no 'a'-arch features)
__device__ __forceinline__ void mma16816(float* c, const uint32_t* a,
                                         uint32_t b0, uint32_t b1) {
    asm volatile(
        "mma.sync.aligned.m16n8k16.row.col.f32.bf16.bf16.f32 "
        "{%0,%1,%2,%3}, {%4,%5,%6,%7}, {%8,%9}, {%0,%1,%2,%3};"
        : "+f"(c[0]), "+f"(c[1]), "+f"(c[2]), "+f"(c[3])
        : "r"(a[0]), "r"(a[1]), "r"(a[2]), "r"(a[3]), "r"(b0), "r"(b1));
}

// ===========================================================================
// qk via mma.sync, double-buffered: E = exp(mask ? -50 : (q.k)/8) -> attn,
// fused row-sum -> g_l. CTA: 128 q-rows, 8 warps = 16 exclusive rows each.
// One __syncthreads per 64-k chunk.
// ===========================================================================
#define KT 64                          // k-rows per chunk
#define KROW_B 144                     // bytes per K smem row (72 bf16, padded)
#define KBUF_B 18432                   // one buffer: hi 9216 + lo 9216
#define SM_CMASK 36864                 // 2 x 64 uchar
#define QK_SMEM  36992

__global__ void __launch_bounds__(256, 2)
qk_mma_kernel(const float* __restrict__ q, const float* __restrict__ kmat,
              const int* __restrict__ mask, float* __restrict__ attn)
{
    __shared__ __align__(16) char smem[QK_SMEM];

    const int tid  = threadIdx.x;
    const int lane = tid & 31, wid = tid >> 5;
    const int g  = lane >> 2, qd = lane & 3;
    const int qt = blockIdx.x, bh = blockIdx.y, b = bh >> 4;

    uint32_t aHi[4][4], aLo[4][4];
    const int r0 = wid * 16 + g;
    {
        const float* qbase = q + ((size_t)bh * NSEQ + (size_t)qt * 128) * DH;
        #pragma unroll
        for (int ks = 0; ks < 4; ++ks) {
            const int c0 = ks * 16 + qd * 2;
            float2 x00 = *(const float2*)(qbase + r0 * DH + c0);
            float2 x10 = *(const float2*)(qbase + (r0 + 8) * DH + c0);
            float2 x01 = *(const float2*)(qbase + r0 * DH + c0 + 8);
            float2 x11 = *(const float2*)(qbase + (r0 + 8) * DH + c0 + 8);
            float h, h2;
            h  = __bfloat162float(__float2bfloat16(x00.x));
            h2 = __bfloat162float(__float2bfloat16(x00.y));
            aHi[ks][0] = pack2(h, h2);
            aLo[ks][0] = pack2(x00.x - h, x00.y - h2);
            h  = __bfloat162float(__float2bfloat16(x10.x));
            h2 = __bfloat162float(__float2bfloat16(x10.y));
            aHi[ks][1] = pack2(h, h2);
            aLo[ks][1] = pack2(x10.x - h, x10.y - h2);
            h  = __bfloat162float(__float2bfloat16(x01.x));
            h2 = __bfloat162float(__float2bfloat16(x01.y));
            aHi[ks][2] = pack2(h, h2);
            aLo[ks][2] = pack2(x01.x - h, x01.y - h2);
            h  = __bfloat162float(__float2bfloat16(x11.x));
            h2 = __bfloat162float(__float2bfloat16(x11.y));
            aHi[ks][3] = pack2(h, h2);
            aLo[ks][3] = pack2(x11.x - h, x11.y - h2);
        }
    }

    const bool rm0 = mask[b * NSEQ + qt * 128 + r0] != 0;
    const bool rm1 = mask[b * NSEQ + qt * 128 + r0 + 8] != 0;
    float lsum0 = 0.f, lsum1 = 0.f;

    float* abase = attn + ((size_t)bh * NSEQ + (size_t)qt * 128) * NSEQ;
    const float* kball = kmat + (size_t)bh * NSEQ * DH;

    const int kr  = tid >> 2;
    const int kc0 = (tid & 3) * 16;
    float4 kReg[4];
    int    mreg = 0;
    {
        const float* kb = kball + (size_t)kr * DH + kc0;
        #pragma unroll
        for (int u = 0; u < 4; ++u) kReg[u] = *(const float4*)(kb + 4 * u);
        if (tid < KT) mreg = mask[b * NSEQ + tid];
    }

    for (int kt = 0; kt < NSEQ / KT; ++kt) {
        const int cur = kt & 1;
        char* kbuf = smem + (size_t)cur * KBUF_B;
        unsigned char* cmaskA = (unsigned char*)(smem + SM_CMASK + cur * 64);

        // ---- commit prefetched chunk kt into buf[cur] ----
        // (last reader of buf[cur] was iter kt-2's MMA; iter kt-1's barrier
        //  separates us from it -> safe with ONE sync per chunk)
        {
            char* hB = kbuf + (size_t)kr * KROW_B;
            char* lB = kbuf + 9216 + (size_t)kr * KROW_B;
            #pragma unroll
            for (int u4 = 0; u4 < 4; ++u4) {
                float4 x = kReg[u4];
                float h0 = __bfloat162float(__float2bfloat16(x.x));
                float h1 = __bfloat162float(__float2bfloat16(x.y));
                float h2 = __bfloat162float(__float2bfloat16(x.z));
                float h3 = __bfloat162float(__float2bfloat16(x.w));
                const int c = kc0 + u4 * 4;
                *(uint32_t*)(hB + c * 2)       = pack2(h0, h1);
                *(uint32_t*)(hB + (c + 2) * 2) = pack2(h2, h3);
                *(uint32_t*)(lB + c * 2)       = pack2(x.x - h0, x.y - h1);
                *(uint32_t*)(lB + (c + 2) * 2) = pack2(x.z - h2, x.w - h3);
            }
            if (tid < KT) cmaskA[tid] = (unsigned char)(mreg != 0);
        }

        // ---- prefetch chunk kt+1 into registers ----
        {
            const int nkt = (kt + 1 < NSEQ / KT) ? kt + 1 : kt;
            const float* kb = kball + (size_t)(nkt * KT + kr) * DH + kc0;
            #pragma unroll
            for (int u = 0; u < 4; ++u) kReg[u] = *(const float4*)(kb + 4 * u);
            if (tid < KT) mreg = mask[b * NSEQ + nkt * KT + tid];
        }

        __syncthreads();   // buf[cur] committed by all warps

        // ---- MMA: 8 n-tiles x 4 k-steps x 3 products ----
        float acc[8][4];
        #pragma unroll
        for (int nt = 0; nt < 8; ++nt)
            #pragma unroll
            for (int u = 0; u < 4; ++u) acc[nt][u] = 0.f;

        #pragma unroll
        for (int nt = 0; nt < 8; ++nt) {
            const int nrow = nt * 8 + g;
            const char* krH = kbuf + (size_t)nrow * KROW_B;
            const char* krL = kbuf + 9216 + (size_t)nrow * KROW_B;
            #pragma unroll
            for (int ks = 0; ks < 4; ++ks) {
                const int koff = (ks * 16 + qd * 2) * 2;
                uint32_t bh0 = *(const uint32_t*)(krH + koff);
                uint32_t bh1 = *(const uint32_t*)(krH + koff + 16);
                uint32_t bl0 = *(const uint32_t*)(krL + koff);
                uint32_t bl1 = *(const uint32_t*)(krL + koff + 16);
                mma16816(acc[nt], aHi[ks], bh0, bh1);
                mma16816(acc[nt], aHi[ks], bl0, bl1);
                mma16816(acc[nt], aLo[ks], bh0, bh1);
            }
        }

        // ---- epilogue: exp + mask + row-sum + direct float2 stores ----
        #pragma unroll
        for (int nt = 0; nt < 8; ++nt) {
            const int col0 = nt * 8 + qd * 2;
            const uint16_t mm = *(const uint16_t*)(cmaskA + col0);
            const bool m0 = (mm & 0xffu) != 0, m1 = (mm >> 8) != 0;
            float* c = acc[nt];
            float e0 = (rm0 || m0) ? EPSM : __expf(c[0] * 0.125f);
            float e1 = (rm0 || m1) ? EPSM : __expf(c[1] * 0.125f);
            float e2 = (rm1 || m0) ? EPSM : __expf(c[2] * 0.125f);
            float e3 = (rm1 || m1) ? EPSM : __expf(c[3] * 0.125f);
            lsum0 += e0 + e1;
            lsum1 += e2 + e3;
            float* dst = abase + (size_t)r0 * NSEQ + kt * KT + col0;
            *(float2*)dst              = make_float2(e0, e1);
            *(float2*)(dst + 8 * NSEQ) = make_float2(e2, e3);
        }
    }

    lsum0 += __shfl_xor_sync(0xffffffffu, lsum0, 1);
    lsum0 += __shfl_xor_sync(0xffffffffu, lsum0, 2);
    lsum1 += __shfl_xor_sync(0xffffffffu, lsum1, 1);
    lsum1 += __shfl_xor_sync(0xffffffffu, lsum1, 2);
    if (qd == 0) {
        g_l[bh * NSEQ + qt * 128 + r0]     = lsum0;
        g_l[bh * NSEQ + qt * 128 + r0 + 8] = lsum1;
    }
}

// ===========================================================================
// pv via mma.sync, double-buffered: p = E/l (written back as attn),
// O = P.V (bf16 hi/lo). One __syncthreads per 32-k chunk.
// ===========================================================================
#define PKT 32                          // k per chunk
#define VSTR 72                         // words per kw-row (64 + 8 pad)
#define PV_NW 16                        // kw rows per chunk (PKT/2)

__global__ void __launch_bounds__(256, 2)
pv_mma_kernel(const float* __restrict__ v, float* __restrict__ attn,
              float* __restrict__ out)
{
    __shared__ __align__(16) uint32_t vtHi[2][PV_NW * VSTR];
    __shared__ __align__(16) uint32_t vtLo[2][PV_NW * VSTR];

    const int tid  = threadIdx.x;
    const int lane = tid & 31, wid = tid >> 5;
    const int g = lane >> 2, qd = lane & 3;
    const int qt = blockIdx.x, bh = blockIdx.y;

    const int r0 = wid * 16 + g;                  // rows r0, r0+8 (warp-exclusive)
    const float rl0 = 1.f / g_l[bh * NSEQ + qt * 128 + r0];
    const float rl1 = 1.f / g_l[bh * NSEQ + qt * 128 + r0 + 8];

    float* abase = attn + ((size_t)bh * NSEQ + (size_t)qt * 128) * NSEQ;
    const float* vbase = v + (size_t)bh * NSEQ * DH;

    const int vp = tid >> 4;          // k-pair 0..15
    const int d0 = (tid & 15) * 4;    // d-slice

    // ---- prefetch chunk 0 ----
    float4 vA, vB;
    float2 eReg[2][4];
    {
        const float* vb = vbase + (size_t)(2 * vp) * DH + d0;
        vA = *(const float4*)vb;
        vB = *(const float4*)(vb + DH);
        #pragma unroll
        for (int ks = 0; ks < 2; ++ks) {
            const float* ep = abase + (size_t)r0 * NSEQ + ks * 16 + qd * 2;
            eReg[ks][0] = *(const float2*)(ep);
            eReg[ks][1] = *(const float2*)(ep + 8 * NSEQ);
            eReg[ks][2] = *(const float2*)(ep + 8);
            eReg[ks][3] = *(const float2*)(ep + 8 * NSEQ + 8);
        }
    }

    float acc[8][4];
    #pragma unroll
    for (int nt = 0; nt < 8; ++nt)
        #pragma unroll
        for (int u = 0; u < 4; ++u) acc[nt][u] = 0.f;

    for (int kt = 0; kt < NSEQ / PKT; ++kt) {
        const int cur = kt & 1;
        const int nkt = (kt + 1 < NSEQ / PKT) ? kt + 1 : kt;

        // ---- commit staged V chunk kt into buf[cur] (safe: see qk note) ----
        {
            float a4[4] = {vA.x, vA.y, vA.z, vA.w};
            float b4[4] = {vB.x, vB.y, vB.z, vB.w};
            uint32_t* hRow = &vtHi[cur][vp * VSTR + d0];
            uint32_t* lRow = &vtLo[cur][vp * VSTR + d0];
            #pragma unroll
            for (int e = 0; e < 4; ++e) {
                float ha = __bfloat162float(__float2bfloat16(a4[e]));
                float hb = __bfloat162float(__float2bfloat16(b4[e]));
                hRow[e] = pack2(ha, hb);
                lRow[e] = pack2(a4[e] - ha, b4[e] - hb);
            }
        }
        // ---- prefetch V chunk kt+1 ----
        {
            const float* vb = vbase + (size_t)(nkt * PKT + 2 * vp) * DH + d0;
            vA = *(const float4*)vb;
            vB = *(const float4*)(vb + DH);
        }

        __syncthreads();   // buf[cur] committed

        // ---- build P fragments from chunk kt's E; write P back to attn ----
        uint32_t pHi[2][4], pLo[2][4];
        #pragma unroll
        for (int ks = 0; ks < 2; ++ks) {
            float p0x = eReg[ks][0].x * rl0, p0y = eReg[ks][0].y * rl0;
            float p1x = eReg[ks][1].x * rl1, p1y = eReg[ks][1].y * rl1;
            float p2x = eReg[ks][2].x * rl0, p2y = eReg[ks][2].y * rl0;
            float p3x = eReg[ks][3].x * rl1, p3y = eReg[ks][3].y * rl1;
            float* pp = abase + (size_t)r0 * NSEQ + kt * PKT + ks * 16 + qd * 2;
            *(float2*)(pp)                = make_float2(p0x, p0y);
            *(float2*)(pp + 8 * NSEQ)     = make_float2(p1x, p1y);
            *(float2*)(pp + 8)            = make_float2(p2x, p2y);
            *(float2*)(pp + 8 * NSEQ + 8) = make_float2(p3x, p3y);
            float h, h2;
            h  = __bfloat162float(__float2bfloat16(p0x));
            h2 = __bfloat162float(__float2bfloat16(p0y));
            pHi[ks][0] = pack2(h, h2); pLo[ks][0] = pack2(p0x - h, p0y - h2);
            h  = __bfloat162float(__float2bfloat16(p1x));
            h2 = __bfloat162float(__float2bfloat16(p1y));
            pHi[ks][1] = pack2(h, h2); pLo[ks][1] = pack2(p1x - h, p1y - h2);
            h  = __bfloat162float(__float2bfloat16(p2x));
            h2 = __bfloat162float(__float2bfloat16(p2y));
            pHi[ks][2] = pack2(h, h2); pLo[ks][2] = pack2(p2x - h, p2y - h2);
            h  = __bfloat162float(__float2bfloat16(p3x));
            h2 = __bfloat162float(__float2bfloat16(p3y));
            pHi[ks][3] = pack2(h, h2); pLo[ks][3] = pack2(p3x - h, p3y - h2);
        }

        // ---- prefetch E fragments for chunk kt+1 (hidden behind MMAs) ----
        #pragma unroll
        for (int ks = 0; ks < 2; ++ks) {
            const float* ep = abase + (size_t)r0 * NSEQ + nkt * PKT
                            + ks * 16 + qd * 2;
            eReg[ks][0] = *(const float2*)(ep);
            eReg[ks][1] = *(const float2*)(ep + 8 * NSEQ);
            eReg[ks][2] = *(const float2*)(ep + 8);
            eReg[ks][3] = *(const float2*)(ep + 8 * NSEQ + 8);
        }

        // ---- MMA: 8 d-tiles x 2 k-steps x 3 products ----
        #pragma unroll
        for (int nt = 0; nt < 8; ++nt) {
            const int d = nt * 8 + g;
            #pragma unroll
            for (int ks = 0; ks < 2; ++ks) {
                const int kw0 = ks * 8 + qd;
                uint32_t bh0 = vtHi[cur][kw0 * VSTR + d];
                uint32_t bh1 = vtHi[cur][(kw0 + 4) * VSTR + d];
                uint32_t bl0 = vtLo[cur][kw0 * VSTR + d];
                uint32_t bl1 = vtLo[cur][(kw0 + 4) * VSTR + d];
                mma16816(acc[nt], pHi[ks], bh0, bh1);
                mma16816(acc[nt], pHi[ks], bl0, bl1);
                mma16816(acc[nt], pLo[ks], bh0, bh1);
            }
        }
    }

    // ---- O stores ----
    float* obase = out + ((size_t)bh * NSEQ + (size_t)qt * 128) * DH;
    #pragma unroll
    for (int nt = 0; nt < 8; ++nt) {
        float* op = obase + (size_t)r0 * DH + nt * 8 + qd * 2;
        *(float2*)op            = make_float2(acc[nt][0], acc[nt][1]);
        *(float2*)(op + 8 * DH) = make_float2(acc[nt][2], acc[nt][3]);
    }
}

extern "C" void kernel_launch(void* const* d_in, const int* in_sizes, int n_in,
                              void* d_out, int out_size)
{
    const float* q    = (const float*)d_in[0];
    const float* kmat = (const float*)d_in[1];
    const float* v    = (const float*)d_in[2];
    const int*   mask = (const int*)d_in[3];

    float* out  = (float*)d_out;                  // [B,H,N,D] first (tuple order)
    float* attn = out + (size_t)NBH * NSEQ * DH;  // [B,H,N,N] second

    qk_mma_kernel<<<dim3(NSEQ / 128, NBH), 256>>>(q, kmat, mask, attn);
    pv_mma_kernel<<<dim3(NSEQ / 128, NBH), 256>>>(v, attn, out);
}

// round 13
// speedup vs baseline: 1.1601x; 1.1601x over previous
#include <cuda_runtime.h>
#include <cuda_bf16.h>
#include <cstdint>

#define NSEQ 2048
#define DH   64
#define NBH  32      // B*H
#define EPSM 1.928749848e-22f   // expf(-50)
#define UNIP (1.0f / 2048.0f)   // uniform P for fully-masked rows (exact)

static __device__ float g_l[NBH * NSEQ];

// pack2(lo, hi): low 16 bits = bf16(lo), high = bf16(hi)
__device__ __forceinline__ uint32_t pack2(float lo, float hi) {
    uint32_t r;  // PTX: first src -> high half, second -> low half
    asm("cvt.rn.bf16x2.f32 %0, %1, %2;" : "=r"(r) : "f"(hi), "f"(lo));
    return r;
}

// portable warp-level bf16 MMA, fp32 accum (sm_80+; no 'a'-arch features)
__device__ __forceinline__ void mma16816(float* c, const uint32_t* a,
                                         uint32_t b0, uint32_t b1) {
    asm volatile(
        "mma.sync.aligned.m16n8k16.row.col.f32.bf16.bf16.f32 "
        "{%0,%1,%2,%3}, {%4,%5,%6,%7}, {%8,%9}, {%0,%1,%2,%3};"
        : "+f"(c[0]), "+f"(c[1]), "+f"(c[2]), "+f"(c[3])
        : "r"(a[0]), "r"(a[1]), "r"(a[2]), "r"(a[3]), "r"(b0), "r"(b1));
}

// ===========================================================================
// qk via mma.sync, double-buffered: E = exp(mask ? -50 : (q.k)/8) -> attn,
// fused row-sum -> g_l. Fully-masked q-rows skip exp/store entirely (pv
// reconstructs their uniform softmax without reading E).
// ===========================================================================
#define KT 64                          // k-rows per chunk
#define KROW_B 144                     // bytes per K smem row (72 bf16, padded)
#define KBUF_B 18432                   // one buffer: hi 9216 + lo 9216
#define SM_CMASK 36864                 // 2 x 64 uchar
#define QK_SMEM  36992

__global__ void __launch_bounds__(256, 2)
qk_mma_kernel(const float* __restrict__ q, const float* __restrict__ kmat,
              const int* __restrict__ mask, float* __restrict__ attn)
{
    __shared__ __align__(16) char smem[QK_SMEM];

    const int tid  = threadIdx.x;
    const int lane = tid & 31, wid = tid >> 5;
    const int g  = lane >> 2, qd = lane & 3;
    const int qt = blockIdx.x, bh = blockIdx.y, b = bh >> 4;

    uint32_t aHi[4][4], aLo[4][4];
    const int r0 = wid * 16 + g;
    {
        const float* qbase = q + ((size_t)bh * NSEQ + (size_t)qt * 128) * DH;
        #pragma unroll
        for (int ks = 0; ks < 4; ++ks) {
            const int c0 = ks * 16 + qd * 2;
            float2 x00 = *(const float2*)(qbase + r0 * DH + c0);
            float2 x10 = *(const float2*)(qbase + (r0 + 8) * DH + c0);
            float2 x01 = *(const float2*)(qbase + r0 * DH + c0 + 8);
            float2 x11 = *(const float2*)(qbase + (r0 + 8) * DH + c0 + 8);
            float h, h2;
            h  = __bfloat162float(__float2bfloat16(x00.x));
            h2 = __bfloat162float(__float2bfloat16(x00.y));
            aHi[ks][0] = pack2(h, h2);
            aLo[ks][0] = pack2(x00.x - h, x00.y - h2);
            h  = __bfloat162float(__float2bfloat16(x10.x));
            h2 = __bfloat162float(__float2bfloat16(x10.y));
            aHi[ks][1] = pack2(h, h2);
            aLo[ks][1] = pack2(x10.x - h, x10.y - h2);
            h  = __bfloat162float(__float2bfloat16(x01.x));
            h2 = __bfloat162float(__float2bfloat16(x01.y));
            aHi[ks][2] = pack2(h, h2);
            aLo[ks][2] = pack2(x01.x - h, x01.y - h2);
            h  = __bfloat162float(__float2bfloat16(x11.x));
            h2 = __bfloat162float(__float2bfloat16(x11.y));
            aHi[ks][3] = pack2(h, h2);
            aLo[ks][3] = pack2(x11.x - h, x11.y - h2);
        }
    }

    const bool rm0 = mask[b * NSEQ + qt * 128 + r0] != 0;
    const bool rm1 = mask[b * NSEQ + qt * 128 + r0 + 8] != 0;
    float lsum0 = 0.f, lsum1 = 0.f;

    float* abase = attn + ((size_t)bh * NSEQ + (size_t)qt * 128) * NSEQ;
    const float* kball = kmat + (size_t)bh * NSEQ * DH;

    const int kr  = tid >> 2;
    const int kc0 = (tid & 3) * 16;
    float4 kReg[4];
    int    mreg = 0;
    {
        const float* kb = kball + (size_t)kr * DH + kc0;
        #pragma unroll
        for (int u = 0; u < 4; ++u) kReg[u] = *(const float4*)(kb + 4 * u);
        if (tid < KT) mreg = mask[b * NSEQ + tid];
    }

    for (int kt = 0; kt < NSEQ / KT; ++kt) {
        const int cur = kt & 1;
        char* kbuf = smem + (size_t)cur * KBUF_B;
        unsigned char* cmaskA = (unsigned char*)(smem + SM_CMASK + cur * 64);

        // ---- commit prefetched chunk kt into buf[cur] ----
        {
            char* hB = kbuf + (size_t)kr * KROW_B;
            char* lB = kbuf + 9216 + (size_t)kr * KROW_B;
            #pragma unroll
            for (int u4 = 0; u4 < 4; ++u4) {
                float4 x = kReg[u4];
                float h0 = __bfloat162float(__float2bfloat16(x.x));
                float h1 = __bfloat162float(__float2bfloat16(x.y));
                float h2 = __bfloat162float(__float2bfloat16(x.z));
                float h3 = __bfloat162float(__float2bfloat16(x.w));
                const int c = kc0 + u4 * 4;
                *(uint32_t*)(hB + c * 2)       = pack2(h0, h1);
                *(uint32_t*)(hB + (c + 2) * 2) = pack2(h2, h3);
                *(uint32_t*)(lB + c * 2)       = pack2(x.x - h0, x.y - h1);
                *(uint32_t*)(lB + (c + 2) * 2) = pack2(x.z - h2, x.w - h3);
            }
            if (tid < KT) cmaskA[tid] = (unsigned char)(mreg != 0);
        }

        // ---- prefetch chunk kt+1 into registers ----
        {
            const int nkt = (kt + 1 < NSEQ / KT) ? kt + 1 : kt;
            const float* kb = kball + (size_t)(nkt * KT + kr) * DH + kc0;
            #pragma unroll
            for (int u = 0; u < 4; ++u) kReg[u] = *(const float4*)(kb + 4 * u);
            if (tid < KT) mreg = mask[b * NSEQ + nkt * KT + tid];
        }

        __syncthreads();   // buf[cur] committed by all warps

        // ---- MMA: 8 n-tiles x 4 k-steps x 3 products ----
        float acc[8][4];
        #pragma unroll
        for (int nt = 0; nt < 8; ++nt)
            #pragma unroll
            for (int u = 0; u < 4; ++u) acc[nt][u] = 0.f;

        #pragma unroll
        for (int nt = 0; nt < 8; ++nt) {
            const int nrow = nt * 8 + g;
            const char* krH = kbuf + (size_t)nrow * KROW_B;
            const char* krL = kbuf + 9216 + (size_t)nrow * KROW_B;
            #pragma unroll
            for (int ks = 0; ks < 4; ++ks) {
                const int koff = (ks * 16 + qd * 2) * 2;
                uint32_t bh0 = *(const uint32_t*)(krH + koff);
                uint32_t bh1 = *(const uint32_t*)(krH + koff + 16);
                uint32_t bl0 = *(const uint32_t*)(krL + koff);
                uint32_t bl1 = *(const uint32_t*)(krL + koff + 16);
                mma16816(acc[nt], aHi[ks], bh0, bh1);
                mma16816(acc[nt], aHi[ks], bl0, bl1);
                mma16816(acc[nt], aLo[ks], bh0, bh1);
            }
        }

        // ---- epilogue: exp + col-mask + row-sum; SKIP masked rows ----
        #pragma unroll
        for (int nt = 0; nt < 8; ++nt) {
            const int col0 = nt * 8 + qd * 2;
            const uint16_t mm = *(const uint16_t*)(cmaskA + col0);
            const bool m0 = (mm & 0xffu) != 0, m1 = (mm >> 8) != 0;
            float* c = acc[nt];
            float* dst = abase + (size_t)r0 * NSEQ + kt * KT + col0;
            if (!rm0) {
                float e0 = m0 ? EPSM : __expf(c[0] * 0.125f);
                float e1 = m1 ? EPSM : __expf(c[1] * 0.125f);
                lsum0 += e0 + e1;
                *(float2*)dst = make_float2(e0, e1);
            }
            if (!rm1) {
                float e2 = m0 ? EPSM : __expf(c[2] * 0.125f);
                float e3 = m1 ? EPSM : __expf(c[3] * 0.125f);
                lsum1 += e2 + e3;
                *(float2*)(dst + 8 * NSEQ) = make_float2(e2, e3);
            }
        }
    }

    lsum0 += __shfl_xor_sync(0xffffffffu, lsum0, 1);
    lsum0 += __shfl_xor_sync(0xffffffffu, lsum0, 2);
    lsum1 += __shfl_xor_sync(0xffffffffu, lsum1, 1);
    lsum1 += __shfl_xor_sync(0xffffffffu, lsum1, 2);
    if (qd == 0) {
        g_l[bh * NSEQ + qt * 128 + r0]     = rm0 ? 2048.0f * EPSM : lsum0;
        g_l[bh * NSEQ + qt * 128 + r0 + 8] = rm1 ? 2048.0f * EPSM : lsum1;
    }
}

// ===========================================================================
// pv via mma.sync, double-buffered: p = E/l (written back as attn),
// O = P.V (bf16 hi/lo). Fully-masked rows: P = 1/2048 constant — no E read.
// ===========================================================================
#define PKT 32                          // k per chunk
#define VSTR 72                         // words per kw-row (64 + 8 pad)
#define PV_NW 16                        // kw rows per chunk (PKT/2)

__global__ void __launch_bounds__(256, 2)
pv_mma_kernel(const float* __restrict__ v, const int* __restrict__ mask,
              float* __restrict__ attn, float* __restrict__ out)
{
    __shared__ __align__(16) uint32_t vtHi[2][PV_NW * VSTR];
    __shared__ __align__(16) uint32_t vtLo[2][PV_NW * VSTR];

    const int tid  = threadIdx.x;
    const int lane = tid & 31, wid = tid >> 5;
    const int g = lane >> 2, qd = lane & 3;
    const int qt = blockIdx.x, bh = blockIdx.y, b = bh >> 4;

    const int r0 = wid * 16 + g;                  // rows r0, r0+8 (warp-exclusive)
    const bool rm0 = mask[b * NSEQ + qt * 128 + r0] != 0;
    const bool rm1 = mask[b * NSEQ + qt * 128 + r0 + 8] != 0;
    const float rl0 = rm0 ? 0.f : 1.f / g_l[bh * NSEQ + qt * 128 + r0];
    const float rl1 = rm1 ? 0.f : 1.f / g_l[bh * NSEQ + qt * 128 + r0 + 8];

    float* abase = attn + ((size_t)bh * NSEQ + (size_t)qt * 128) * NSEQ;
    const float* vbase = v + (size_t)bh * NSEQ * DH;

    const int vp = tid >> 4;          // k-pair 0..15
    const int d0 = (tid & 15) * 4;    // d-slice

    // ---- prefetch chunk 0 (E loads only for unmasked rows) ----
    float4 vA, vB;
    float2 eReg[2][4] = {};
    {
        const float* vb = vbase + (size_t)(2 * vp) * DH + d0;
        vA = *(const float4*)vb;
        vB = *(const float4*)(vb + DH);
        #pragma unroll
        for (int ks = 0; ks < 2; ++ks) {
            const float* ep = abase + (size_t)r0 * NSEQ + ks * 16 + qd * 2;
            if (!rm0) {
                eReg[ks][0] = *(const float2*)(ep);
                eReg[ks][2] = *(const float2*)(ep + 8);
            }
            if (!rm1) {
                eReg[ks][1] = *(const float2*)(ep + 8 * NSEQ);
                eReg[ks][3] = *(const float2*)(ep + 8 * NSEQ + 8);
            }
        }
    }

    float acc[8][4];
    #pragma unroll
    for (int nt = 0; nt < 8; ++nt)
        #pragma unroll
        for (int u = 0; u < 4; ++u) acc[nt][u] = 0.f;

    for (int kt = 0; kt < NSEQ / PKT; ++kt) {
        const int cur = kt & 1;
        const int nkt = (kt + 1 < NSEQ / PKT) ? kt + 1 : kt;

        // ---- commit staged V chunk kt into buf[cur] ----
        {
            float a4[4] = {vA.x, vA.y, vA.z, vA.w};
            float b4[4] = {vB.x, vB.y, vB.z, vB.w};
            uint32_t* hRow = &vtHi[cur][vp * VSTR + d0];
            uint32_t* lRow = &vtLo[cur][vp * VSTR + d0];
            #pragma unroll
            for (int e = 0; e < 4; ++e) {
                float ha = __bfloat162float(__float2bfloat16(a4[e]));
                float hb = __bfloat162float(__float2bfloat16(b4[e]));
                hRow[e] = pack2(ha, hb);
                lRow[e] = pack2(a4[e] - ha, b4[e] - hb);
            }
        }
        // ---- prefetch V chunk kt+1 ----
        {
            const float* vb = vbase + (size_t)(nkt * PKT + 2 * vp) * DH + d0;
            vA = *(const float4*)vb;
            vB = *(const float4*)(vb + DH);
        }

        __syncthreads();   // buf[cur] committed

        // ---- build P fragments for chunk kt; write P back to attn ----
        uint32_t pHi[2][4], pLo[2][4];
        #pragma unroll
        for (int ks = 0; ks < 2; ++ks) {
            float p0x, p0y, p2x, p2y, p1x, p1y, p3x, p3y;
            if (rm0) {
                p0x = p0y = p2x = p2y = UNIP;
            } else {
                p0x = eReg[ks][0].x * rl0; p0y = eReg[ks][0].y * rl0;
                p2x = eReg[ks][2].x * rl0; p2y = eReg[ks][2].y * rl0;
            }
            if (rm1) {
                p1x = p1y = p3x = p3y = UNIP;
            } else {
                p1x = eReg[ks][1].x * rl1; p1y = eReg[ks][1].y * rl1;
                p3x = eReg[ks][3].x * rl1; p3y = eReg[ks][3].y * rl1;
            }
            float* pp = abase + (size_t)r0 * NSEQ + kt * PKT + ks * 16 + qd * 2;
            *(float2*)(pp)                = make_float2(p0x, p0y);
            *(float2*)(pp + 8 * NSEQ)     = make_float2(p1x, p1y);
            *(float2*)(pp + 8)            = make_float2(p2x, p2y);
            *(float2*)(pp + 8 * NSEQ + 8) = make_float2(p3x, p3y);
            float h, h2;
            h  = __bfloat162float(__float2bfloat16(p0x));
            h2 = __bfloat162float(__float2bfloat16(p0y));
            pHi[ks][0] = pack2(h, h2); pLo[ks][0] = pack2(p0x - h, p0y - h2);
            h  = __bfloat162float(__float2bfloat16(p1x));
            h2 = __bfloat162float(__float2bfloat16(p1y));
            pHi[ks][1] = pack2(h, h2); pLo[ks][1] = pack2(p1x - h, p1y - h2);
            h  = __bfloat162float(__float2bfloat16(p2x));
            h2 = __bfloat162float(__float2bfloat16(p2y));
            pHi[ks][2] = pack2(h, h2); pLo[ks][2] = pack2(p2x - h, p2y - h2);
            h  = __bfloat162float(__float2bfloat16(p3x));
            h2 = __bfloat162float(__float2bfloat16(p3y));
            pHi[ks][3] = pack2(h, h2); pLo[ks][3] = pack2(p3x - h, p3y - h2);
        }

        // ---- prefetch E fragments for chunk kt+1 (unmasked rows only) ----
        #pragma unroll
        for (int ks = 0; ks < 2; ++ks) {
            const float* ep = abase + (size_t)r0 * NSEQ + nkt * PKT
                            + ks * 16 + qd * 2;
            if (!rm0) {
                eReg[ks][0] = *(const float2*)(ep);
                eReg[ks][2] = *(const float2*)(ep + 8);
            }
            if (!rm1) {
                eReg[ks][1] = *(const float2*)(ep + 8 * NSEQ);
                eReg[ks][3] = *(const float2*)(ep + 8 * NSEQ + 8);
            }
        }

        // ---- MMA: 8 d-tiles x 2 k-steps x 3 products ----
        #pragma unroll
        for (int nt = 0; nt < 8; ++nt) {
            const int d = nt * 8 + g;
            #pragma unroll
            for (int ks = 0; ks < 2; ++ks) {
                const int kw0 = ks * 8 + qd;
                uint32_t bh0 = vtHi[cur][kw0 * VSTR + d];
                uint32_t bh1 = vtHi[cur][(kw0 + 4) * VSTR + d];
                uint32_t bl0 = vtLo[cur][kw0 * VSTR + d];
                uint32_t bl1 = vtLo[cur][(kw0 + 4) * VSTR + d];
                mma16816(acc[nt], pHi[ks], bh0, bh1);
                mma16816(acc[nt], pHi[ks], bl0, bl1);
                mma16816(acc[nt], pLo[ks], bh0, bh1);
            }
        }
    }

    // ---- O stores ----
    float* obase = out + ((size_t)bh * NSEQ + (size_t)qt * 128) * DH;
    #pragma unroll
    for (int nt = 0; nt < 8; ++nt) {
        float* op = obase + (size_t)r0 * DH + nt * 8 + qd * 2;
        *(float2*)op            = make_float2(acc[nt][0], acc[nt][1]);
        *(float2*)(op + 8 * DH) = make_float2(acc[nt][2], acc[nt][3]);
    }
}

extern "C" void kernel_launch(void* const* d_in, const int* in_sizes, int n_in,
                              void* d_out, int out_size)
{
    const float* q    = (const float*)d_in[0];
    const float* kmat = (const float*)d_in[1];
    const float* v    = (const float*)d_in[2];
    const int*   mask = (const int*)d_in[3];

    float* out  = (float*)d_out;                  // [B,H,N,D] first (tuple order)
    float* attn = out + (size_t)NBH * NSEQ * DH;  // [B,H,N,N] second

    qk_mma_kernel<<<dim3(NSEQ / 128, NBH), 256>>>(q, kmat, mask, attn);
    pv_mma_kernel<<<dim3(NSEQ / 128, NBH), 256>>>(v, mask, attn, out);
}